// round 7
// baseline (speedup 1.0000x reference)
#include <cuda_runtime.h>
#include <cstdint>

#define NN 50000
#define EE 800000
#define CIN 32
#define CH 64
#define COUT 16
#define TE 128   // edges per block in edgeconv

// ---------------- scratch (device globals; no allocs) ----------------
__device__ float d_dinv[NN];
__device__ int   d_cnt[NN];
__device__ int   d_rowptr[NN + 1];
__device__ int   d_fill[NN];
__device__ int   d_src[EE];    // CSR: source node per edge, sorted by col
__device__ int   d_ccol[EE];   // CSR: col per edge (sorted, runs contiguous)
__device__ int   d_row32[EE];
__device__ int   d_col32[EE];
__device__ float d_y[NN * CIN];
__device__ float d_h1[NN * CH];
__device__ float d_P[NN * CH];
__device__ float d_Q[NN * CH];
__device__ float d_h2[NN * CH];
__device__ float d_z[NN * COUT];

// ---------------- kernels ----------------

// zero d_cnt and d_h2
__global__ void k_init() {
    int t = blockIdx.x * blockDim.x + threadIdx.x;
    if (t < NN) d_cnt[t] = 0;
    if (t < NN * CH) d_h2[t] = 0.f;
}

// edge_index is int32 on device (JAX x64 disabled downcasts int64->int32).
// Guarded: out-of-range indices are clamped-skipped rather than faulting.
__global__ void k_prep(const int* __restrict__ ei) {
    int e = blockIdx.x * blockDim.x + threadIdx.x;
    if (e >= EE) return;
    int r = ei[e];
    int c = ei[EE + e];
    if ((unsigned)r >= NN) r = 0;
    if ((unsigned)c >= NN) c = 0;
    d_row32[e] = r;
    d_col32[e] = c;
    atomicAdd(&d_cnt[c], 1);
}

// single-block exclusive scan -> rowptr, fill cursors, dinv
__global__ void k_scan() {
    __shared__ int sh[1024];
    const int CHK = (NN + 1023) / 1024;  // 49
    int tid = threadIdx.x;
    int base = tid * CHK;
    int s = 0;
    for (int i = 0; i < CHK; i++) {
        int idx = base + i;
        if (idx < NN) s += d_cnt[idx];
    }
    sh[tid] = s;
    __syncthreads();
    for (int off = 1; off < 1024; off <<= 1) {
        int v = (tid >= off) ? sh[tid - off] : 0;
        __syncthreads();
        sh[tid] += v;
        __syncthreads();
    }
    int run = sh[tid] - s;  // exclusive prefix
    for (int i = 0; i < CHK; i++) {
        int idx = base + i;
        if (idx < NN) {
            d_rowptr[idx] = run;
            d_fill[idx]   = run;
            d_dinv[idx]   = rsqrtf((float)d_cnt[idx] + 1.0f);
            run += d_cnt[idx];
        }
    }
    if (tid == 0) d_rowptr[NN] = EE;
}

__global__ void k_scatter() {
    int e = blockIdx.x * blockDim.x + threadIdx.x;
    if (e >= EE) return;
    int c = d_col32[e];
    int pos = atomicAdd(&d_fill[c], 1);
    d_src[pos]  = d_row32[e];
    d_ccol[pos] = c;
}

// GCN1 input-space aggregation: y[c] = dinv[c]*(sum_r dinv[r]*x[r] + dinv[c]*x[c]); warp per node
__global__ void k_gcn1_gather(const float* __restrict__ x) {
    int w = (blockIdx.x * blockDim.x + threadIdx.x) >> 5;
    int lane = threadIdx.x & 31;
    if (w >= NN) return;
    int c = w;
    int beg = d_rowptr[c], end = d_rowptr[c + 1];
    float s = 0.f;
    for (int i = beg; i < end; i++) {
        int r = __ldg(&d_src[i]);
        float wr = __ldg(&d_dinv[r]);
        s += wr * __ldg(&x[r * CIN + lane]);
    }
    float dc = d_dinv[c];
    float xc = x[c * CIN + lane];
    d_y[c * CIN + lane] = dc * (s + dc * xc);
}

// h1 = tanh(y @ W1 + b1)
__global__ void k_gcn1_mm(const float* __restrict__ w, const float* __restrict__ b) {
    __shared__ float ws[CIN * CH];
    __shared__ float bs[CH];
    for (int i = threadIdx.x; i < CIN * CH; i += blockDim.x) ws[i] = w[i];
    if (threadIdx.x < CH) bs[threadIdx.x] = b[threadIdx.x];
    __syncthreads();
    int t = blockIdx.x * blockDim.x + threadIdx.x;
    if (t >= NN * CH) return;
    int c = t >> 6, k = t & 63;
    const float* yr = &d_y[c * CIN];
    float acc = bs[k];
#pragma unroll
    for (int j = 0; j < CIN; j++) acc += yr[j] * ws[j * CH + k];
    d_h1[t] = tanhf(acc);
}

// P = h1 @ (W1a - W1b) + b1,  Q = h1 @ W1b   (edge_w1 is [128,64]: top 64 rows = W1a)
__global__ void k_pq(const float* __restrict__ w1, const float* __restrict__ b1) {
    __shared__ float wa[CH * CH];  // W1a - W1b
    __shared__ float wb[CH * CH];  // W1b
    __shared__ float bs[CH];
    for (int i = threadIdx.x; i < CH * CH; i += blockDim.x) {
        float lo = w1[i];
        float hi = w1[CH * CH + i];
        wa[i] = lo - hi;
        wb[i] = hi;
    }
    if (threadIdx.x < CH) bs[threadIdx.x] = b1[threadIdx.x];
    __syncthreads();
    int t = blockIdx.x * blockDim.x + threadIdx.x;
    if (t >= NN * CH) return;
    int c = t >> 6, k = t & 63;
    const float* hr = &d_h1[c * CH];
    float p = bs[k], q = 0.f;
#pragma unroll 8
    for (int j = 0; j < CH; j++) {
        float h = hr[j];
        p += h * wa[j * CH + k];
        q += h * wb[j * CH + k];
    }
    d_P[t] = p;
    d_Q[t] = q;
}

// EdgeConv: per 128-edge tile: U = relu(P[col]+Q[row]); M = U @ W2; segment-max(+b2) into h2
__global__ void __launch_bounds__(256) k_edgeconv(const float* __restrict__ w2,
                                                  const float* __restrict__ b2) {
    extern __shared__ float sm[];
    float* u   = sm;                   // [64][132] transposed u (j-major), reused as m [128][64]
    float* w2s = sm + 64 * 132;        // [64][64]
    float* b2s = w2s + 64 * 64;        // [64]
    int*   cols = (int*)(b2s + 64);    // [128]
    int*   srcs = cols + TE;           // [128]
    float* msh = u;

    int tid = threadIdx.x;
    for (int i = tid; i < 64 * 64; i += 256) w2s[i] = w2[i];
    if (tid < 64) b2s[tid] = b2[tid];
    int ebase = blockIdx.x * TE;
    if (tid < TE) {
        int idx = ebase + tid;
        if (idx < EE) { cols[tid] = d_ccol[idx]; srcs[tid] = d_src[idx]; }
        else          { cols[tid] = -1;          srcs[tid] = 0; }
    }
    __syncthreads();

    // Phase A: u[j][e] = relu(P[c][j] + Q[r][j])
    {
        int j = tid & 63;
        int esub = tid >> 6;  // 0..3
        for (int e = esub; e < TE; e += 4) {
            int c = cols[e], r = srcs[e];
            float v = 0.f;
            if (c >= 0) v = fmaxf(__ldg(&d_P[c * 64 + j]) + __ldg(&d_Q[r * 64 + j]), 0.f);
            u[j * 132 + e] = v;
        }
    }
    __syncthreads();

    // Phase B: M[128][64] = U^T @ W2; thread computes 4 edges x 8 k
    int cg = tid & 7;   // k block: cg*8 .. +8
    int rg = tid >> 3;  // edge block: rg*4 .. +4
    float acc[4][8];
#pragma unroll
    for (int i = 0; i < 4; i++)
#pragma unroll
        for (int n = 0; n < 8; n++) acc[i][n] = 0.f;

#pragma unroll 4
    for (int jj = 0; jj < 64; jj++) {
        float4 a  = *(const float4*)&u[jj * 132 + rg * 4];
        float4 bA = *(const float4*)&w2s[jj * 64 + cg * 8];
        float4 bB = *(const float4*)&w2s[jj * 64 + cg * 8 + 4];
        float av[4] = {a.x, a.y, a.z, a.w};
#pragma unroll
        for (int i = 0; i < 4; i++) {
            acc[i][0] += av[i] * bA.x;
            acc[i][1] += av[i] * bA.y;
            acc[i][2] += av[i] * bA.z;
            acc[i][3] += av[i] * bA.w;
            acc[i][4] += av[i] * bB.x;
            acc[i][5] += av[i] * bB.y;
            acc[i][6] += av[i] * bB.z;
            acc[i][7] += av[i] * bB.w;
        }
    }
    __syncthreads();  // everyone done reading u before overwriting with m

#pragma unroll
    for (int i = 0; i < 4; i++) {
        int e = rg * 4 + i;
        *(float4*)&msh[e * 64 + cg * 8]     = make_float4(acc[i][0], acc[i][1], acc[i][2], acc[i][3]);
        *(float4*)&msh[e * 64 + cg * 8 + 4] = make_float4(acc[i][4], acc[i][5], acc[i][6], acc[i][7]);
    }
    __syncthreads();

    // Phase C: per-(col-run, k) max, flush with atomicMax (positive floats as ints; h2 init 0)
    {
        int k = tid & 63;
        int part = tid >> 6;  // 0..3, 32 edges each
        float mx = -3.0e38f;
        int cur = -1;
        for (int e = part * 32; e < part * 32 + 32; e++) {
            int c = cols[e];
            if (c != cur) {
                if (cur >= 0) {
                    float v = mx + b2s[k];
                    if (v > 0.f) atomicMax((int*)&d_h2[cur * 64 + k], __float_as_int(v));
                }
                cur = c;
                mx = -3.0e38f;
            }
            mx = fmaxf(mx, msh[e * 64 + k]);
        }
        if (cur >= 0) {
            float v = mx + b2s[k];
            if (v > 0.f) atomicMax((int*)&d_h2[cur * 64 + k], __float_as_int(v));
        }
    }
}

// z = h2 @ gcn2_w  (bias folded into final gather)
__global__ void k_z(const float* __restrict__ w) {
    __shared__ float ws[CH * COUT];
    for (int i = threadIdx.x; i < CH * COUT; i += blockDim.x) ws[i] = w[i];
    __syncthreads();
    int t = blockIdx.x * blockDim.x + threadIdx.x;
    if (t >= NN * COUT) return;
    int c = t >> 4, k = t & 15;
    const float* hr = &d_h2[c * CH];
    float acc = 0.f;
#pragma unroll 8
    for (int j = 0; j < CH; j++) acc += hr[j] * ws[j * COUT + k];
    d_z[t] = acc;
}

// out[c] = dinv[c]*(sum_r dinv[r]*z[r] + dinv[c]*z[c]) + b ; warp per node (lanes 0..15)
__global__ void k_out(const float* __restrict__ b, float* __restrict__ out) {
    int w = (blockIdx.x * blockDim.x + threadIdx.x) >> 5;
    int lane = threadIdx.x & 31;
    if (w >= NN || lane >= COUT) return;
    int c = w;
    int beg = d_rowptr[c], end = d_rowptr[c + 1];
    float s = 0.f;
    for (int i = beg; i < end; i++) {
        int r = __ldg(&d_src[i]);
        s += __ldg(&d_dinv[r]) * __ldg(&d_z[r * COUT + lane]);
    }
    float dc = d_dinv[c];
    out[c * COUT + lane] = dc * (s + dc * d_z[c * COUT + lane]) + b[lane];
}

// ---------------- launch ----------------
extern "C" void kernel_launch(void* const* d_in, const int* in_sizes, int n_in,
                              void* d_out, int out_size) {
    const float* x   = (const float*)d_in[0];
    const int*   ei  = (const int*)d_in[1];     // int32 (JAX x64 disabled)
    const float* g1w = (const float*)d_in[2];
    const float* g1b = (const float*)d_in[3];
    const float* e1w = (const float*)d_in[4];
    const float* e1b = (const float*)d_in[5];
    const float* e2w = (const float*)d_in[6];
    const float* e2b = (const float*)d_in[7];
    const float* g2w = (const float*)d_in[8];
    const float* g2b = (const float*)d_in[9];
    float* out = (float*)d_out;

    k_init<<<(NN * CH + 255) / 256, 256>>>();
    k_prep<<<(EE + 255) / 256, 256>>>(ei);
    k_scan<<<1, 1024>>>();
    k_scatter<<<(EE + 255) / 256, 256>>>();
    k_gcn1_gather<<<(NN * 32 + 255) / 256, 256>>>(x);
    k_gcn1_mm<<<(NN * CH + 255) / 256, 256>>>(g1w, g1b);
    k_pq<<<(NN * CH + 255) / 256, 256>>>(e1w, e1b);

    int smem = (64 * 132 + 64 * 64 + 64) * (int)sizeof(float) + 2 * TE * (int)sizeof(int);
    cudaFuncSetAttribute(k_edgeconv, cudaFuncAttributeMaxDynamicSharedMemorySize, smem);
    k_edgeconv<<<(EE + TE - 1) / TE, 256, smem>>>(e2w, e2b);

    k_z<<<(NN * COUT + 255) / 256, 256>>>(g2w);
    k_out<<<(NN * 32 + 255) / 256, 256>>>(g2b, out);
}

// round 9
// speedup vs baseline: 1.2881x; 1.2881x over previous
#include <cuda_runtime.h>
#include <cstdint>

#define NN 50000
#define EE 800000
#define CIN 32
#define CH 64
#define COUT 16
#define TE 128   // edges per block in edgeconv
#define SB 1024  // scan block size
#define SNB ((NN + SB - 1) / SB)   // 49

// ---------------- scratch (device globals; no allocs) ----------------
__device__ float d_dinv[NN];
__device__ int   d_cnt[NN];
__device__ int   d_rowptr[NN + 1];
__device__ int   d_fill[NN];
__device__ int   d_bsum[64];
__device__ int   d_boff[64];
__device__ int2  d_edge[EE];   // CSR: {src,col} per edge, grouped by col
__device__ float d_y[NN * CIN];
__device__ float d_h1[NN * CH];
__device__ float d_P[NN * CH];
__device__ float d_Q[NN * CH];
__device__ float d_h2[NN * CH];
__device__ float d_z[NN * COUT];

// ---------------- f32x2 packed helpers (FFMA2: 2x fp32 FMA/inst, bit-exact) ----
__device__ __forceinline__ void fma2(unsigned long long& d, unsigned long long a,
                                     unsigned long long b) {
    asm("fma.rn.f32x2 %0, %1, %2, %0;" : "+l"(d) : "l"(a), "l"(b));
}
__device__ __forceinline__ unsigned long long pack2(float lo, float hi) {
    unsigned long long r;
    asm("mov.b64 %0, {%1, %2};" : "=l"(r) : "f"(lo), "f"(hi));
    return r;
}
__device__ __forceinline__ unsigned long long add2(unsigned long long a,
                                                   unsigned long long b) {
    unsigned long long r;
    asm("add.rn.f32x2 %0, %1, %2;" : "=l"(r) : "l"(a), "l"(b));
    return r;
}

// ---------------- kernels ----------------

__global__ void k_init() {
    int t = blockIdx.x * blockDim.x + threadIdx.x;
    if (t < NN) d_cnt[t] = 0;
    if (t < NN * CH) d_h2[t] = 0.f;
}

// histogram over col (edge_index is int32 on device: JAX x64-disabled)
__global__ void k_prep(const int* __restrict__ ei) {
    int e = blockIdx.x * blockDim.x + threadIdx.x;
    if (e >= EE) return;
    int c = ei[EE + e];
    if ((unsigned)c >= NN) c = 0;
    atomicAdd(&d_cnt[c], 1);
}

// parallel exclusive scan of d_cnt: block reduce -> scan of block sums -> re-scan
__global__ void k_scan1() {
    __shared__ int sh[SB];
    int idx = blockIdx.x * SB + threadIdx.x;
    sh[threadIdx.x] = (idx < NN) ? d_cnt[idx] : 0;
    __syncthreads();
    for (int off = SB / 2; off > 0; off >>= 1) {
        if (threadIdx.x < off) sh[threadIdx.x] += sh[threadIdx.x + off];
        __syncthreads();
    }
    if (threadIdx.x == 0) d_bsum[blockIdx.x] = sh[0];
}

__global__ void k_scan2() {
    __shared__ int sh[64];
    int t = threadIdx.x;
    int v = (t < SNB) ? d_bsum[t] : 0;
    sh[t] = v;
    __syncthreads();
    for (int off = 1; off < 64; off <<= 1) {
        int u = (t >= off) ? sh[t - off] : 0;
        __syncthreads();
        sh[t] += u;
        __syncthreads();
    }
    d_boff[t] = sh[t] - v;
}

__global__ void k_scan3() {
    __shared__ int sh[SB];
    int t = threadIdx.x;
    int idx = blockIdx.x * SB + t;
    int v = (idx < NN) ? d_cnt[idx] : 0;
    sh[t] = v;
    __syncthreads();
    for (int off = 1; off < SB; off <<= 1) {
        int u = (t >= off) ? sh[t - off] : 0;
        __syncthreads();
        sh[t] += u;
        __syncthreads();
    }
    if (idx < NN) {
        int pos = d_boff[blockIdx.x] + sh[t] - v;
        d_rowptr[idx] = pos;
        d_fill[idx]   = pos;
        d_dinv[idx]   = rsqrtf((float)v + 1.0f);
    }
    if (idx == 0) d_rowptr[NN] = EE;
}

// scatter edges into CSR order (order within a col-run is irrelevant: sum/max)
__global__ void k_scatter(const int* __restrict__ ei) {
    int e = blockIdx.x * blockDim.x + threadIdx.x;
    if (e >= EE) return;
    int r = ei[e];
    int c = ei[EE + e];
    if ((unsigned)r >= NN) r = 0;
    if ((unsigned)c >= NN) c = 0;
    int pos = atomicAdd(&d_fill[c], 1);
    d_edge[pos] = make_int2(r, c);
}

// GCN1 input-space aggregation: y[c] = dinv[c]*(sum_r dinv[r]*x[r] + dinv[c]*x[c]); warp/node
__global__ void k_gcn1_gather(const float* __restrict__ x) {
    int w = (blockIdx.x * blockDim.x + threadIdx.x) >> 5;
    int lane = threadIdx.x & 31;
    if (w >= NN) return;
    int c = w;
    int beg = d_rowptr[c], end = d_rowptr[c + 1];
    float s = 0.f;
    for (int i = beg; i < end; i++) {
        int2 e = __ldg(&d_edge[i]);
        s += __ldg(&d_dinv[e.x]) * __ldg(&x[e.x * CIN + lane]);
    }
    float dc = d_dinv[c];
    d_y[c * CIN + lane] = dc * (s + dc * x[c * CIN + lane]);
}

// h1 = tanh(y @ W1 + b1)
__global__ void k_gcn1_mm(const float* __restrict__ w, const float* __restrict__ b) {
    __shared__ float ws[CIN * CH];
    __shared__ float bs[CH];
    for (int i = threadIdx.x; i < CIN * CH; i += blockDim.x) ws[i] = w[i];
    if (threadIdx.x < CH) bs[threadIdx.x] = b[threadIdx.x];
    __syncthreads();
    int t = blockIdx.x * blockDim.x + threadIdx.x;
    if (t >= NN * CH) return;
    int c = t >> 6, k = t & 63;
    const float* yr = &d_y[c * CIN];
    float acc = bs[k];
#pragma unroll
    for (int j = 0; j < CIN; j++) acc += yr[j] * ws[j * CH + k];
    d_h1[t] = tanhf(acc);
}

// [P|Q] = h1 @ [W1a-W1b | W1b] as a register-tiled GEMM with f32x2.
// Block: 64 nodes x 128 cols; thread: 4 nodes x 8 cols.
__global__ void __launch_bounds__(256) k_pq(const float* __restrict__ w1,
                                            const float* __restrict__ b1) {
    extern __shared__ float pqsm[];
    float* wsm = pqsm;              // [64][128]: cols 0-63 = W1a-W1b, 64-127 = W1b
    float* bsm = wsm + 64 * 128;    // [64]
    float* ht  = bsm + 64;          // [64][68] transposed h1 tile
    int tid = threadIdx.x;

    for (int i = tid; i < 64 * 64; i += 256) {
        int j = i >> 6, k = i & 63;
        float hi = w1[(64 + j) * 64 + k];
        wsm[j * 128 + k]      = w1[j * 64 + k] - hi;
        wsm[j * 128 + 64 + k] = hi;
    }
    if (tid < 64) bsm[tid] = b1[tid];
    int nb0 = blockIdx.x * 64;
    for (int i = tid; i < 64 * 64; i += 256) {
        int node = i >> 6, j = i & 63;
        int g = nb0 + node;
        ht[j * 68 + node] = (g < NN) ? d_h1[g * 64 + j] : 0.f;
    }
    __syncthreads();

    int cg = tid & 15;   // col group: cg*8 .. +8 (of 128)
    int rg = tid >> 4;   // node group: rg*4 .. +4 (of 64)
    unsigned long long acc[4][4];
#pragma unroll
    for (int i = 0; i < 4; i++)
#pragma unroll
        for (int n = 0; n < 4; n++) acc[i][n] = 0ULL;

#pragma unroll 4
    for (int jj = 0; jj < 64; jj++) {
        float4 a = *(const float4*)&ht[jj * 68 + rg * 4];
        const unsigned long long* bp =
            (const unsigned long long*)&wsm[jj * 128 + cg * 8];
        unsigned long long b0 = bp[0], b1v = bp[1], b2 = bp[2], b3 = bp[3];
        float av[4] = {a.x, a.y, a.z, a.w};
#pragma unroll
        for (int i = 0; i < 4; i++) {
            unsigned long long ap = pack2(av[i], av[i]);
            fma2(acc[i][0], ap, b0);
            fma2(acc[i][1], ap, b1v);
            fma2(acc[i][2], ap, b2);
            fma2(acc[i][3], ap, b3);
        }
    }

    if (cg < 8) {
        unsigned long long bb[4];
#pragma unroll
        for (int n = 0; n < 4; n++) bb[n] = pack2(bsm[cg * 8 + 2 * n], bsm[cg * 8 + 2 * n + 1]);
#pragma unroll
        for (int i = 0; i < 4; i++) {
            int g = nb0 + rg * 4 + i;
            if (g >= NN) continue;
            unsigned long long* dst = (unsigned long long*)&d_P[g * 64 + cg * 8];
#pragma unroll
            for (int n = 0; n < 4; n++) dst[n] = add2(acc[i][n], bb[n]);
        }
    } else {
#pragma unroll
        for (int i = 0; i < 4; i++) {
            int g = nb0 + rg * 4 + i;
            if (g >= NN) continue;
            unsigned long long* dst = (unsigned long long*)&d_Q[g * 64 + (cg - 8) * 8];
#pragma unroll
            for (int n = 0; n < 4; n++) dst[n] = acc[i][n];
        }
    }
}

// EdgeConv: per 128-edge tile: U = relu(P[col]+Q[row]); M = U @ W2 (f32x2); seg-max into h2
__global__ void __launch_bounds__(256) k_edgeconv(const float* __restrict__ w2,
                                                  const float* __restrict__ b2) {
    extern __shared__ float sm[];
    float* u   = sm;                   // [64][132] transposed u, reused as m [128][64]
    float* w2s = sm + 64 * 132;        // [64][64]
    float* b2s = w2s + 64 * 64;        // [64]
    int*   cols = (int*)(b2s + 64);    // [128]
    int*   srcs = cols + TE;           // [128]
    float* msh = u;

    int tid = threadIdx.x;
    for (int i = tid; i < 64 * 64; i += 256) w2s[i] = w2[i];
    if (tid < 64) b2s[tid] = b2[tid];
    int ebase = blockIdx.x * TE;
    if (tid < TE) {
        int idx = ebase + tid;
        if (idx < EE) { int2 e = d_edge[idx]; srcs[tid] = e.x; cols[tid] = e.y; }
        else          { cols[tid] = -1;       srcs[tid] = 0; }
    }
    __syncthreads();

    // Phase A: u[j][e] = relu(P[c][j] + Q[r][j])
    {
        int j = tid & 63;
        int esub = tid >> 6;
        for (int e = esub; e < TE; e += 4) {
            int c = cols[e], r = srcs[e];
            float v = 0.f;
            if (c >= 0) v = fmaxf(__ldg(&d_P[c * 64 + j]) + __ldg(&d_Q[r * 64 + j]), 0.f);
            u[j * 132 + e] = v;
        }
    }
    __syncthreads();

    // Phase B: M = U^T @ W2, f32x2 packed (4 edges x 8 k per thread)
    int cg = tid & 7;
    int rg = tid >> 3;
    unsigned long long acc[4][4];
#pragma unroll
    for (int i = 0; i < 4; i++)
#pragma unroll
        for (int n = 0; n < 4; n++) acc[i][n] = 0ULL;

#pragma unroll 4
    for (int jj = 0; jj < 64; jj++) {
        float4 a = *(const float4*)&u[jj * 132 + rg * 4];
        const unsigned long long* bp =
            (const unsigned long long*)&w2s[jj * 64 + cg * 8];
        unsigned long long b0 = bp[0], b1v = bp[1], b2 = bp[2], b3 = bp[3];
        float av[4] = {a.x, a.y, a.z, a.w};
#pragma unroll
        for (int i = 0; i < 4; i++) {
            unsigned long long ap = pack2(av[i], av[i]);
            fma2(acc[i][0], ap, b0);
            fma2(acc[i][1], ap, b1v);
            fma2(acc[i][2], ap, b2);
            fma2(acc[i][3], ap, b3);
        }
    }
    __syncthreads();  // all reads of u done before overwrite with m

#pragma unroll
    for (int i = 0; i < 4; i++) {
        int e = rg * 4 + i;
        unsigned long long* mp = (unsigned long long*)&msh[e * 64 + cg * 8];
#pragma unroll
        for (int n = 0; n < 4; n++) mp[n] = acc[i][n];
    }
    __syncthreads();

    // Phase C: per-(col-run, k) max; flush via atomicMax on positive-float-as-int
    {
        int k = tid & 63;
        int part = tid >> 6;
        float mx = -3.0e38f;
        int cur = -1;
        for (int e = part * 32; e < part * 32 + 32; e++) {
            int c = cols[e];
            if (c != cur) {
                if (cur >= 0) {
                    float v = mx + b2s[k];
                    if (v > 0.f) atomicMax((int*)&d_h2[cur * 64 + k], __float_as_int(v));
                }
                cur = c;
                mx = -3.0e38f;
            }
            mx = fmaxf(mx, msh[e * 64 + k]);
        }
        if (cur >= 0) {
            float v = mx + b2s[k];
            if (v > 0.f) atomicMax((int*)&d_h2[cur * 64 + k], __float_as_int(v));
        }
    }
}

// z = h2 @ gcn2_w  (bias folded into final gather)
__global__ void k_z(const float* __restrict__ w) {
    __shared__ float ws[CH * COUT];
    for (int i = threadIdx.x; i < CH * COUT; i += blockDim.x) ws[i] = w[i];
    __syncthreads();
    int t = blockIdx.x * blockDim.x + threadIdx.x;
    if (t >= NN * COUT) return;
    int c = t >> 4, k = t & 15;
    const float* hr = &d_h2[c * CH];
    float acc = 0.f;
#pragma unroll 8
    for (int j = 0; j < CH; j++) acc += hr[j] * ws[j * COUT + k];
    d_z[t] = acc;
}

// out[c] = dinv[c]*(sum_r dinv[r]*z[r] + dinv[c]*z[c]) + b ; warp/node (lanes 0..15)
__global__ void k_out(const float* __restrict__ b, float* __restrict__ out) {
    int w = (blockIdx.x * blockDim.x + threadIdx.x) >> 5;
    int lane = threadIdx.x & 31;
    if (w >= NN || lane >= COUT) return;
    int c = w;
    int beg = d_rowptr[c], end = d_rowptr[c + 1];
    float s = 0.f;
    for (int i = beg; i < end; i++) {
        int2 e = __ldg(&d_edge[i]);
        s += __ldg(&d_dinv[e.x]) * __ldg(&d_z[e.x * COUT + lane]);
    }
    float dc = d_dinv[c];
    out[c * COUT + lane] = dc * (s + dc * d_z[c * COUT + lane]) + b[lane];
}

// ---------------- launch ----------------
extern "C" void kernel_launch(void* const* d_in, const int* in_sizes, int n_in,
                              void* d_out, int out_size) {
    const float* x   = (const float*)d_in[0];
    const int*   ei  = (const int*)d_in[1];
    const float* g1w = (const float*)d_in[2];
    const float* g1b = (const float*)d_in[3];
    const float* e1w = (const float*)d_in[4];
    const float* e1b = (const float*)d_in[5];
    const float* e2w = (const float*)d_in[6];
    const float* e2b = (const float*)d_in[7];
    const float* g2w = (const float*)d_in[8];
    const float* g2b = (const float*)d_in[9];
    float* out = (float*)d_out;

    k_init<<<(NN * CH + 255) / 256, 256>>>();
    k_prep<<<(EE + 255) / 256, 256>>>(ei);
    k_scan1<<<SNB, SB>>>();
    k_scan2<<<1, 64>>>();
    k_scan3<<<SNB, SB>>>();
    k_scatter<<<(EE + 255) / 256, 256>>>(ei);
    k_gcn1_gather<<<(NN * 32 + 255) / 256, 256>>>(x);
    k_gcn1_mm<<<(NN * CH + 255) / 256, 256>>>(g1w, g1b);

    int pqsmem = (64 * 128 + 64 + 64 * 68) * (int)sizeof(float);
    cudaFuncSetAttribute(k_pq, cudaFuncAttributeMaxDynamicSharedMemorySize, pqsmem);
    k_pq<<<(NN + 63) / 64, 256, pqsmem>>>(e1w, e1b);

    int smem = (64 * 132 + 64 * 64 + 64) * (int)sizeof(float) + 2 * TE * (int)sizeof(int);
    cudaFuncSetAttribute(k_edgeconv, cudaFuncAttributeMaxDynamicSharedMemorySize, smem);
    k_edgeconv<<<(EE + TE - 1) / TE, 256, smem>>>(e2w, e2b);

    k_z<<<(NN * COUT + 255) / 256, 256>>>(g2w);
    k_out<<<(NN * 32 + 255) / 256, 256>>>(g2b, out);
}

// round 11
// speedup vs baseline: 1.4840x; 1.1521x over previous
#include <cuda_runtime.h>
#include <cstdint>

#define NN 50000
#define EE 800000
#define CIN 32
#define CH 64
#define COUT 16
#define TE 128   // edges per tile in edgeconv
#define NT ((EE + TE - 1) / TE)
#define SB 1024  // scan block size
#define SNB ((NN + SB - 1) / SB)   // 49

// ---------------- scratch (device globals; zero-initialized at load) ----------------
__device__ float d_dinv[NN];
__device__ int   d_cnt[NN];        // re-zeroed by k_scan3 each call
__device__ int   d_rowptr[NN + 1];
__device__ int   d_fill[NN];
__device__ int   d_bsum[64];
__device__ int   d_boff[64];
__device__ int2  d_edge[EE];       // CSR: {src,col}, grouped by col
__device__ float d_h1[NN * CH];
__device__ float d_P[NN * CH];
__device__ float d_Q[NN * CH];
__device__ float d_h2[NN * CH];    // re-zeroed by k_z each call
__device__ float d_z[NN * COUT];

// ---------------- f32x2 packed helpers (FFMA2: 2x fp32 FMA/inst, bit-exact) ----
__device__ __forceinline__ void fma2(unsigned long long& d, unsigned long long a,
                                     unsigned long long b) {
    asm("fma.rn.f32x2 %0, %1, %2, %0;" : "+l"(d) : "l"(a), "l"(b));
}
__device__ __forceinline__ unsigned long long pack2(float lo, float hi) {
    unsigned long long r;
    asm("mov.b64 %0, {%1, %2};" : "=l"(r) : "f"(lo), "f"(hi));
    return r;
}
__device__ __forceinline__ unsigned long long add2(unsigned long long a,
                                                   unsigned long long b) {
    unsigned long long r;
    asm("add.rn.f32x2 %0, %1, %2;" : "=l"(r) : "l"(a), "l"(b));
    return r;
}

// ---------------- kernels ----------------

// histogram over col (edge_index is int32 on device)
__global__ void k_prep(const int* __restrict__ ei) {
    int e = blockIdx.x * blockDim.x + threadIdx.x;
    if (e >= EE) return;
    int c = ei[EE + e];
    if ((unsigned)c >= NN) c = 0;
    atomicAdd(&d_cnt[c], 1);
}

__global__ void k_scan1() {
    __shared__ int sh[SB];
    int idx = blockIdx.x * SB + threadIdx.x;
    sh[threadIdx.x] = (idx < NN) ? d_cnt[idx] : 0;
    __syncthreads();
    for (int off = SB / 2; off > 0; off >>= 1) {
        if (threadIdx.x < off) sh[threadIdx.x] += sh[threadIdx.x + off];
        __syncthreads();
    }
    if (threadIdx.x == 0) d_bsum[blockIdx.x] = sh[0];
}

__global__ void k_scan2() {
    __shared__ int sh[64];
    int t = threadIdx.x;
    int v = (t < SNB) ? d_bsum[t] : 0;
    sh[t] = v;
    __syncthreads();
    for (int off = 1; off < 64; off <<= 1) {
        int u = (t >= off) ? sh[t - off] : 0;
        __syncthreads();
        sh[t] += u;
        __syncthreads();
    }
    d_boff[t] = sh[t] - v;
}

__global__ void k_scan3() {
    __shared__ int sh[SB];
    int t = threadIdx.x;
    int idx = blockIdx.x * SB + t;
    int v = (idx < NN) ? d_cnt[idx] : 0;
    sh[t] = v;
    __syncthreads();
    for (int off = 1; off < SB; off <<= 1) {
        int u = (t >= off) ? sh[t - off] : 0;
        __syncthreads();
        sh[t] += u;
        __syncthreads();
    }
    if (idx < NN) {
        int pos = d_boff[blockIdx.x] + sh[t] - v;
        d_rowptr[idx] = pos;
        d_fill[idx]   = pos;
        d_dinv[idx]   = rsqrtf((float)v + 1.0f);
        d_cnt[idx]    = 0;   // reset for next call (graph replays)
    }
    if (idx == 0) d_rowptr[NN] = EE;
}

__global__ void k_scatter(const int* __restrict__ ei) {
    int e = blockIdx.x * blockDim.x + threadIdx.x;
    if (e >= EE) return;
    int r = ei[e];
    int c = ei[EE + e];
    if ((unsigned)r >= NN) r = 0;
    if ((unsigned)c >= NN) c = 0;
    int pos = atomicAdd(&d_fill[c], 1);
    d_edge[pos] = make_int2(r, c);
}

// Fused GCN1: gather (warp per node) + matmul + tanh. Persistent.
__global__ void __launch_bounds__(256) k_h1(const float* __restrict__ x,
                                            const float* __restrict__ w,
                                            const float* __restrict__ bb) {
    __shared__ float ws[CIN * CH];
    __shared__ float bs[CH];
    __shared__ float ys[8][CIN];
    int tid = threadIdx.x;
    for (int i = tid; i < CIN * CH; i += 256) ws[i] = w[i];
    if (tid < CH) bs[tid] = bb[tid];
    __syncthreads();
    int warp = tid >> 5, lane = tid & 31;
    for (int c = blockIdx.x * 8 + warp; c < NN; c += gridDim.x * 8) {
        int beg = d_rowptr[c], end = d_rowptr[c + 1];
        float s0 = 0.f, s1 = 0.f;
        int i = beg;
        for (; i + 1 < end; i += 2) {
            int2 e0 = __ldg(&d_edge[i]);
            int2 e1 = __ldg(&d_edge[i + 1]);
            s0 += __ldg(&d_dinv[e0.x]) * __ldg(&x[e0.x * CIN + lane]);
            s1 += __ldg(&d_dinv[e1.x]) * __ldg(&x[e1.x * CIN + lane]);
        }
        if (i < end) {
            int2 e0 = __ldg(&d_edge[i]);
            s0 += __ldg(&d_dinv[e0.x]) * __ldg(&x[e0.x * CIN + lane]);
        }
        float dc = d_dinv[c];
        ys[warp][lane] = dc * (s0 + s1 + dc * x[c * CIN + lane]);
        __syncwarp();
        float a0 = bs[lane], a1 = bs[lane + 32];
#pragma unroll
        for (int j = 0; j < CIN; j++) {
            float yv = ys[warp][j];
            a0 += yv * ws[j * CH + lane];
            a1 += yv * ws[j * CH + lane + 32];
        }
        d_h1[c * CH + lane]      = tanhf(a0);
        d_h1[c * CH + lane + 32] = tanhf(a1);
        __syncwarp();
    }
}

// [P|Q] = h1 @ [W1a-W1b | W1b]: register-tiled GEMM with f32x2.
__global__ void __launch_bounds__(256) k_pq(const float* __restrict__ w1,
                                            const float* __restrict__ b1) {
    extern __shared__ float pqsm[];
    float* wsm = pqsm;              // [64][128]
    float* bsm = wsm + 64 * 128;
    float* ht  = bsm + 64;          // [64][68]
    int tid = threadIdx.x;

    for (int i = tid; i < 64 * 64; i += 256) {
        int j = i >> 6, k = i & 63;
        float hi = w1[(64 + j) * 64 + k];
        wsm[j * 128 + k]      = w1[j * 64 + k] - hi;
        wsm[j * 128 + 64 + k] = hi;
    }
    if (tid < 64) bsm[tid] = b1[tid];
    int nb0 = blockIdx.x * 64;
    for (int i = tid; i < 64 * 64; i += 256) {
        int node = i >> 6, j = i & 63;
        int g = nb0 + node;
        ht[j * 68 + node] = (g < NN) ? d_h1[g * 64 + j] : 0.f;
    }
    __syncthreads();

    int cg = tid & 15;
    int rg = tid >> 4;
    unsigned long long acc[4][4];
#pragma unroll
    for (int i = 0; i < 4; i++)
#pragma unroll
        for (int n = 0; n < 4; n++) acc[i][n] = 0ULL;

#pragma unroll 4
    for (int jj = 0; jj < 64; jj++) {
        float4 a = *(const float4*)&ht[jj * 68 + rg * 4];
        const unsigned long long* bp =
            (const unsigned long long*)&wsm[jj * 128 + cg * 8];
        unsigned long long b0 = bp[0], b1v = bp[1], b2 = bp[2], b3 = bp[3];
        float av[4] = {a.x, a.y, a.z, a.w};
#pragma unroll
        for (int i = 0; i < 4; i++) {
            unsigned long long ap = pack2(av[i], av[i]);
            fma2(acc[i][0], ap, b0);
            fma2(acc[i][1], ap, b1v);
            fma2(acc[i][2], ap, b2);
            fma2(acc[i][3], ap, b3);
        }
    }

    if (cg < 8) {
        unsigned long long bb[4];
#pragma unroll
        for (int n = 0; n < 4; n++) bb[n] = pack2(bsm[cg * 8 + 2 * n], bsm[cg * 8 + 2 * n + 1]);
#pragma unroll
        for (int i = 0; i < 4; i++) {
            int g = nb0 + rg * 4 + i;
            if (g >= NN) continue;
            unsigned long long* dst = (unsigned long long*)&d_P[g * 64 + cg * 8];
#pragma unroll
            for (int n = 0; n < 4; n++) dst[n] = add2(acc[i][n], bb[n]);
        }
    } else {
#pragma unroll
        for (int i = 0; i < 4; i++) {
            int g = nb0 + rg * 4 + i;
            if (g >= NN) continue;
            unsigned long long* dst = (unsigned long long*)&d_Q[g * 64 + (cg - 8) * 8];
#pragma unroll
            for (int n = 0; n < 4; n++) dst[n] = acc[i][n];
        }
    }
}

// EdgeConv, persistent: W2 in smem once per block; loop over 128-edge tiles.
__global__ void __launch_bounds__(256) k_edgeconv(const float* __restrict__ w2,
                                                  const float* __restrict__ b2) {
    extern __shared__ float sm[];
    float* u   = sm;                   // [64][132] transposed u, reused as m [128][64]
    float* w2s = sm + 64 * 132;        // [64][64]
    float* b2s = w2s + 64 * 64;        // [64]
    int*   cols = (int*)(b2s + 64);    // [128]
    int*   srcs = cols + TE;           // [128]
    float* msh = u;

    int tid = threadIdx.x;
    for (int i = tid; i < 64 * 64; i += 256) w2s[i] = w2[i];
    if (tid < 64) b2s[tid] = b2[tid];

    int cg = tid & 7;
    int rg = tid >> 3;
    int ea  = tid >> 1;          // Phase A: edge
    int jh  = (tid & 1) * 8;     // Phase A: float4-chunk base (8 chunks per half)

    for (int tile = blockIdx.x; tile < NT; tile += gridDim.x) {
        __syncthreads();  // prev iter's Phase C reads of cols/msh complete
        int ebase = tile * TE;
        if (tid < TE) {
            int idx = ebase + tid;
            if (idx < EE) { int2 e = __ldg(&d_edge[idx]); srcs[tid] = e.x; cols[tid] = e.y; }
            else          { cols[tid] = -1;               srcs[tid] = 0; }
        }
        __syncthreads();

        // Phase A: u[j][e] = relu(P[c][j] + Q[r][j]); float4 loads
        {
            int c = cols[ea], r = srcs[ea];
            if (c >= 0) {
                const float4* Pp = (const float4*)&d_P[c * 64];
                const float4* Qp = (const float4*)&d_Q[r * 64];
#pragma unroll
                for (int cc = 0; cc < 8; cc++) {
                    float4 p = __ldg(&Pp[jh + cc]);
                    float4 q = __ldg(&Qp[jh + cc]);
                    int j = (jh + cc) * 4;
                    u[(j + 0) * 132 + ea] = fmaxf(p.x + q.x, 0.f);
                    u[(j + 1) * 132 + ea] = fmaxf(p.y + q.y, 0.f);
                    u[(j + 2) * 132 + ea] = fmaxf(p.z + q.z, 0.f);
                    u[(j + 3) * 132 + ea] = fmaxf(p.w + q.w, 0.f);
                }
            } else {
#pragma unroll
                for (int cc = 0; cc < 8; cc++) {
                    int j = (jh + cc) * 4;
                    u[(j + 0) * 132 + ea] = 0.f;
                    u[(j + 1) * 132 + ea] = 0.f;
                    u[(j + 2) * 132 + ea] = 0.f;
                    u[(j + 3) * 132 + ea] = 0.f;
                }
            }
        }
        __syncthreads();

        // Phase B: M = U^T @ W2, f32x2 (4 edges x 8 k per thread)
        unsigned long long acc[4][4];
#pragma unroll
        for (int i = 0; i < 4; i++)
#pragma unroll
            for (int n = 0; n < 4; n++) acc[i][n] = 0ULL;

#pragma unroll 4
        for (int jj = 0; jj < 64; jj++) {
            float4 a = *(const float4*)&u[jj * 132 + rg * 4];
            const unsigned long long* bp =
                (const unsigned long long*)&w2s[jj * 64 + cg * 8];
            unsigned long long b0 = bp[0], b1v = bp[1], b2 = bp[2], b3 = bp[3];
            float av[4] = {a.x, a.y, a.z, a.w};
#pragma unroll
            for (int i = 0; i < 4; i++) {
                unsigned long long ap = pack2(av[i], av[i]);
                fma2(acc[i][0], ap, b0);
                fma2(acc[i][1], ap, b1v);
                fma2(acc[i][2], ap, b2);
                fma2(acc[i][3], ap, b3);
            }
        }
        __syncthreads();  // all reads of u done before overwrite with m

#pragma unroll
        for (int i = 0; i < 4; i++) {
            int e = rg * 4 + i;
            unsigned long long* mp = (unsigned long long*)&msh[e * 64 + cg * 8];
#pragma unroll
            for (int n = 0; n < 4; n++) mp[n] = acc[i][n];
        }
        __syncthreads();

        // Phase C: per-(col-run, k) max; flush via atomicMax (positive-float-as-int)
        {
            int k = tid & 63;
            int part = tid >> 6;
            float mx = -3.0e38f;
            int cur = -1;
            for (int e = part * 32; e < part * 32 + 32; e++) {
                int c = cols[e];
                if (c != cur) {
                    if (cur >= 0) {
                        float v = mx + b2s[k];
                        if (v > 0.f) atomicMax((int*)&d_h2[cur * 64 + k], __float_as_int(v));
                    }
                    cur = c;
                    mx = -3.0e38f;
                }
                mx = fmaxf(mx, msh[e * 64 + k]);
            }
            if (cur >= 0) {
                float v = mx + b2s[k];
                if (v > 0.f) atomicMax((int*)&d_h2[cur * 64 + k], __float_as_int(v));
            }
        }
    }
}

// z = h2 @ gcn2_w; then zero this block's h2 chunk for next call
__global__ void k_z(const float* __restrict__ w) {
    __shared__ float ws[CH * COUT];
    for (int i = threadIdx.x; i < CH * COUT; i += blockDim.x) ws[i] = w[i];
    __syncthreads();
    int t = blockIdx.x * blockDim.x + threadIdx.x;   // grid exactly NN*COUT
    int c = t >> 4, k = t & 15;
    const float* hr = &d_h2[c * CH];
    float acc = 0.f;
#pragma unroll 8
    for (int j = 0; j < CH; j++) acc += hr[j] * ws[j * COUT + k];
    d_z[t] = acc;
    __syncthreads();
    float4* hz = (float4*)&d_h2[(size_t)blockIdx.x * 1024];
    hz[threadIdx.x] = make_float4(0.f, 0.f, 0.f, 0.f);
}

// out[c] = dinv[c]*(sum_r dinv[r]*z[r] + dinv[c]*z[c]) + b ; 2 nodes per warp
__global__ void k_out(const float* __restrict__ b, float* __restrict__ out) {
    int gw = (blockIdx.x * blockDim.x + threadIdx.x) >> 5;
    int lane = threadIdx.x & 31;
    int c = gw * 2 + (lane >> 4);
    int l = lane & 15;
    if (c >= NN) return;
    int beg = d_rowptr[c], end = d_rowptr[c + 1];
    float s0 = 0.f, s1 = 0.f;
    int i = beg;
    for (; i + 1 < end; i += 2) {
        int2 e0 = __ldg(&d_edge[i]);
        int2 e1 = __ldg(&d_edge[i + 1]);
        s0 += __ldg(&d_dinv[e0.x]) * __ldg(&d_z[e0.x * COUT + l]);
        s1 += __ldg(&d_dinv[e1.x]) * __ldg(&d_z[e1.x * COUT + l]);
    }
    if (i < end) {
        int2 e0 = __ldg(&d_edge[i]);
        s0 += __ldg(&d_dinv[e0.x]) * __ldg(&d_z[e0.x * COUT + l]);
    }
    float dc = d_dinv[c];
    out[c * COUT + l] = dc * (s0 + s1 + dc * d_z[c * COUT + l]) + b[l];
}

// ---------------- launch ----------------
extern "C" void kernel_launch(void* const* d_in, const int* in_sizes, int n_in,
                              void* d_out, int out_size) {
    const float* x   = (const float*)d_in[0];
    const int*   ei  = (const int*)d_in[1];
    const float* g1w = (const float*)d_in[2];
    const float* g1b = (const float*)d_in[3];
    const float* e1w = (const float*)d_in[4];
    const float* e1b = (const float*)d_in[5];
    const float* e2w = (const float*)d_in[6];
    const float* e2b = (const float*)d_in[7];
    const float* g2w = (const float*)d_in[8];
    const float* g2b = (const float*)d_in[9];
    float* out = (float*)d_out;

    k_prep<<<(EE + 255) / 256, 256>>>(ei);
    k_scan1<<<SNB, SB>>>();
    k_scan2<<<1, 64>>>();
    k_scan3<<<SNB, SB>>>();
    k_scatter<<<(EE + 255) / 256, 256>>>(ei);
    k_h1<<<1184, 256>>>(x, g1w, g1b);

    int pqsmem = (64 * 128 + 64 + 64 * 68) * (int)sizeof(float);
    cudaFuncSetAttribute(k_pq, cudaFuncAttributeMaxDynamicSharedMemorySize, pqsmem);
    k_pq<<<(NN + 63) / 64, 256, pqsmem>>>(e1w, e1b);

    int smem = (64 * 132 + 64 * 64 + 64) * (int)sizeof(float) + 2 * TE * (int)sizeof(int);
    cudaFuncSetAttribute(k_edgeconv, cudaFuncAttributeMaxDynamicSharedMemorySize, smem);
    k_edgeconv<<<592, 256, smem>>>(e2w, e2b);

    k_z<<<(NN * COUT + 255) / 256, 256>>>(g2w);
    k_out<<<(NN * 16 + 255) / 256, 256>>>(g2b, out);
}

// round 13
// speedup vs baseline: 1.7784x; 1.1984x over previous
#include <cuda_runtime.h>
#include <cstdint>

#define NN 50000
#define EE 800000
#define CIN 32
#define CH 64
#define COUT 16
#define TE 128   // edges per tile in edgeconv
#define NT ((EE + TE - 1) / TE)
#define SB 1024  // scan block size
#define SNB ((NN + SB - 1) / SB)   // 49

// edgeconv smem layout (float offsets)
#define EC_R0   8704          // region0: u [64][132]=8448 / msh [128][68]=8704 (aliased)
#define EC_W2   EC_R0         // w2s [64][64]
#define EC_B2   (EC_W2 + 4096)
#define EC_COL  (EC_B2 + 64)
#define EC_SRC  (EC_COL + 128)
#define EC_FLTS (EC_SRC + 128)   // 13120 floats = 52480 B

// ---------------- scratch (device globals; zero-initialized at load) ----------------
__device__ float d_dinv[NN];
__device__ int   d_cnt[NN];        // re-zeroed by k_scan3 each call
__device__ int   d_rowptr[NN + 1];
__device__ int   d_fill[NN];
__device__ int   d_bsum[64];
__device__ int   d_boff[64];
__device__ int2  d_edge[EE];       // CSR: {src,col}, grouped by col
__device__ float d_h1[NN * CH];
__device__ float d_P[NN * CH];
__device__ float d_Q[NN * CH];
__device__ float d_h2[NN * CH];    // re-zeroed by k_z each call
__device__ float d_z[NN * COUT];

// ---------------- f32x2 packed helpers (FFMA2: 2x fp32 FMA/inst, bit-exact) ----
__device__ __forceinline__ void fma2(unsigned long long& d, unsigned long long a,
                                     unsigned long long b) {
    asm("fma.rn.f32x2 %0, %1, %2, %0;" : "+l"(d) : "l"(a), "l"(b));
}
__device__ __forceinline__ unsigned long long pack2(float lo, float hi) {
    unsigned long long r;
    asm("mov.b64 %0, {%1, %2};" : "=l"(r) : "f"(lo), "f"(hi));
    return r;
}
__device__ __forceinline__ unsigned long long add2(unsigned long long a,
                                                   unsigned long long b) {
    unsigned long long r;
    asm("add.rn.f32x2 %0, %1, %2;" : "=l"(r) : "l"(a), "l"(b));
    return r;
}

// ---------------- kernels ----------------

// histogram over col (edge_index is int32 on device)
__global__ void k_prep(const int* __restrict__ ei) {
    int e = blockIdx.x * blockDim.x + threadIdx.x;
    if (e >= EE) return;
    int c = ei[EE + e];
    if ((unsigned)c >= NN) c = 0;
    atomicAdd(&d_cnt[c], 1);
}

__global__ void k_scan1() {
    __shared__ int sh[SB];
    int idx = blockIdx.x * SB + threadIdx.x;
    sh[threadIdx.x] = (idx < NN) ? d_cnt[idx] : 0;
    __syncthreads();
    for (int off = SB / 2; off > 0; off >>= 1) {
        if (threadIdx.x < off) sh[threadIdx.x] += sh[threadIdx.x + off];
        __syncthreads();
    }
    if (threadIdx.x == 0) d_bsum[blockIdx.x] = sh[0];
}

__global__ void k_scan2() {
    __shared__ int sh[64];
    int t = threadIdx.x;
    int v = (t < SNB) ? d_bsum[t] : 0;
    sh[t] = v;
    __syncthreads();
    for (int off = 1; off < 64; off <<= 1) {
        int u = (t >= off) ? sh[t - off] : 0;
        __syncthreads();
        sh[t] += u;
        __syncthreads();
    }
    d_boff[t] = sh[t] - v;
}

__global__ void k_scan3() {
    __shared__ int sh[SB];
    int t = threadIdx.x;
    int idx = blockIdx.x * SB + t;
    int v = (idx < NN) ? d_cnt[idx] : 0;
    sh[t] = v;
    __syncthreads();
    for (int off = 1; off < SB; off <<= 1) {
        int u = (t >= off) ? sh[t - off] : 0;
        __syncthreads();
        sh[t] += u;
        __syncthreads();
    }
    if (idx < NN) {
        int pos = d_boff[blockIdx.x] + sh[t] - v;
        d_rowptr[idx] = pos;
        d_fill[idx]   = pos;
        d_dinv[idx]   = rsqrtf((float)v + 1.0f);
        d_cnt[idx]    = 0;   // reset for next call (graph replays)
    }
    if (idx == 0) d_rowptr[NN] = EE;
}

__global__ void k_scatter(const int* __restrict__ ei) {
    int e = blockIdx.x * blockDim.x + threadIdx.x;
    if (e >= EE) return;
    int r = ei[e];
    int c = ei[EE + e];
    if ((unsigned)r >= NN) r = 0;
    if ((unsigned)c >= NN) c = 0;
    int pos = atomicAdd(&d_fill[c], 1);
    d_edge[pos] = make_int2(r, c);
}

// Fused GCN1: gather (warp per node) + matmul + tanh. Persistent.
__global__ void __launch_bounds__(256) k_h1(const float* __restrict__ x,
                                            const float* __restrict__ w,
                                            const float* __restrict__ bb) {
    __shared__ float ws[CIN * CH];
    __shared__ float bs[CH];
    __shared__ float ys[8][CIN];
    int tid = threadIdx.x;
    for (int i = tid; i < CIN * CH; i += 256) ws[i] = w[i];
    if (tid < CH) bs[tid] = bb[tid];
    __syncthreads();
    int warp = tid >> 5, lane = tid & 31;
    for (int c = blockIdx.x * 8 + warp; c < NN; c += gridDim.x * 8) {
        int beg = d_rowptr[c], end = d_rowptr[c + 1];
        float s0 = 0.f, s1 = 0.f;
        int i = beg;
        for (; i + 1 < end; i += 2) {
            int2 e0 = __ldg(&d_edge[i]);
            int2 e1 = __ldg(&d_edge[i + 1]);
            s0 += __ldg(&d_dinv[e0.x]) * __ldg(&x[e0.x * CIN + lane]);
            s1 += __ldg(&d_dinv[e1.x]) * __ldg(&x[e1.x * CIN + lane]);
        }
        if (i < end) {
            int2 e0 = __ldg(&d_edge[i]);
            s0 += __ldg(&d_dinv[e0.x]) * __ldg(&x[e0.x * CIN + lane]);
        }
        float dc = d_dinv[c];
        ys[warp][lane] = dc * (s0 + s1 + dc * x[c * CIN + lane]);
        __syncwarp();
        float a0 = bs[lane], a1 = bs[lane + 32];
#pragma unroll
        for (int j = 0; j < CIN; j++) {
            float yv = ys[warp][j];
            a0 += yv * ws[j * CH + lane];
            a1 += yv * ws[j * CH + lane + 32];
        }
        d_h1[c * CH + lane]      = tanhf(a0);
        d_h1[c * CH + lane + 32] = tanhf(a1);
        __syncwarp();
    }
}

// [P|Q] = h1 @ [W1a-W1b | W1b]: register-tiled GEMM with f32x2.
__global__ void __launch_bounds__(256) k_pq(const float* __restrict__ w1,
                                            const float* __restrict__ b1) {
    extern __shared__ float pqsm[];
    float* wsm = pqsm;              // [64][128]
    float* bsm = wsm + 64 * 128;
    float* ht  = bsm + 64;          // [64][68]
    int tid = threadIdx.x;

    for (int i = tid; i < 64 * 64; i += 256) {
        int j = i >> 6, k = i & 63;
        float hi = w1[(64 + j) * 64 + k];
        wsm[j * 128 + k]      = w1[j * 64 + k] - hi;
        wsm[j * 128 + 64 + k] = hi;
    }
    if (tid < 64) bsm[tid] = b1[tid];
    int nb0 = blockIdx.x * 64;
    for (int i = tid; i < 64 * 64; i += 256) {
        int node = i >> 6, j = i & 63;
        int g = nb0 + node;
        ht[j * 68 + node] = (g < NN) ? d_h1[g * 64 + j] : 0.f;
    }
    __syncthreads();

    int cg = tid & 15;
    int rg = tid >> 4;
    unsigned long long acc[4][4];
#pragma unroll
    for (int i = 0; i < 4; i++)
#pragma unroll
        for (int n = 0; n < 4; n++) acc[i][n] = 0ULL;

#pragma unroll 4
    for (int jj = 0; jj < 64; jj++) {
        float4 a = *(const float4*)&ht[jj * 68 + rg * 4];
        const unsigned long long* bp =
            (const unsigned long long*)&wsm[jj * 128 + cg * 8];
        unsigned long long b0 = bp[0], b1v = bp[1], b2 = bp[2], b3 = bp[3];
        float av[4] = {a.x, a.y, a.z, a.w};
#pragma unroll
        for (int i = 0; i < 4; i++) {
            unsigned long long ap = pack2(av[i], av[i]);
            fma2(acc[i][0], ap, b0);
            fma2(acc[i][1], ap, b1v);
            fma2(acc[i][2], ap, b2);
            fma2(acc[i][3], ap, b3);
        }
    }

    if (cg < 8) {
        unsigned long long bb[4];
#pragma unroll
        for (int n = 0; n < 4; n++) bb[n] = pack2(bsm[cg * 8 + 2 * n], bsm[cg * 8 + 2 * n + 1]);
#pragma unroll
        for (int i = 0; i < 4; i++) {
            int g = nb0 + rg * 4 + i;
            if (g >= NN) continue;
            unsigned long long* dst = (unsigned long long*)&d_P[g * 64 + cg * 8];
#pragma unroll
            for (int n = 0; n < 4; n++) dst[n] = add2(acc[i][n], bb[n]);
        }
    } else {
#pragma unroll
        for (int i = 0; i < 4; i++) {
            int g = nb0 + rg * 4 + i;
            if (g >= NN) continue;
            unsigned long long* dst = (unsigned long long*)&d_Q[g * 64 + (cg - 8) * 8];
#pragma unroll
            for (int n = 0; n < 4; n++) dst[n] = acc[i][n];
        }
    }
}

// EdgeConv, persistent. Phase B: warp = 8-wide k-slice (b loads warp-broadcast),
// lanes = 4 edges each. Removes the w2s smem-crossbar bound.
__global__ void __launch_bounds__(256) k_edgeconv(const float* __restrict__ w2,
                                                  const float* __restrict__ b2) {
    extern __shared__ float sm[];
    float* u    = sm;                 // [64][132] transposed u
    float* msh  = sm;                 // [128][68], aliases u
    float* w2s  = sm + EC_W2;         // [64][64]
    float* b2s  = sm + EC_B2;         // [64]
    int*   cols = (int*)(sm + EC_COL);
    int*   srcs = (int*)(sm + EC_SRC);

    int tid = threadIdx.x, wid = tid >> 5, lane = tid & 31;
    for (int i = tid; i < 64 * 64; i += 256) w2s[i] = w2[i];
    if (tid < 64) b2s[tid] = b2[tid];

    int ea = tid >> 1;           // Phase A: edge
    int jh = (tid & 1) * 8;      // Phase A: float4-chunk base

    for (int tile = blockIdx.x; tile < NT; tile += gridDim.x) {
        __syncthreads();  // prev iter's Phase C reads of cols/msh complete
        if (tid < TE) {
            int idx = tile * TE + tid;
            if (idx < EE) { int2 e = __ldg(&d_edge[idx]); srcs[tid] = e.x; cols[tid] = e.y; }
            else          { cols[tid] = -1;               srcs[tid] = 0; }
        }
        __syncthreads();

        // Phase A: u[j][e] = relu(P[c][j] + Q[r][j]); float4 loads
        {
            int c = cols[ea], r = srcs[ea];
            if (c >= 0) {
                const float4* Pp = (const float4*)&d_P[c * 64];
                const float4* Qp = (const float4*)&d_Q[r * 64];
#pragma unroll
                for (int cc = 0; cc < 8; cc++) {
                    float4 p = __ldg(&Pp[jh + cc]);
                    float4 q = __ldg(&Qp[jh + cc]);
                    int j = (jh + cc) * 4;
                    u[(j + 0) * 132 + ea] = fmaxf(p.x + q.x, 0.f);
                    u[(j + 1) * 132 + ea] = fmaxf(p.y + q.y, 0.f);
                    u[(j + 2) * 132 + ea] = fmaxf(p.z + q.z, 0.f);
                    u[(j + 3) * 132 + ea] = fmaxf(p.w + q.w, 0.f);
                }
            } else {
#pragma unroll
                for (int cc = 0; cc < 8; cc++) {
                    int j = (jh + cc) * 4;
                    u[(j + 0) * 132 + ea] = 0.f;
                    u[(j + 1) * 132 + ea] = 0.f;
                    u[(j + 2) * 132 + ea] = 0.f;
                    u[(j + 3) * 132 + ea] = 0.f;
                }
            }
        }
        __syncthreads();

        // Phase B: warp wid owns k-slice wid*8..+8; lane owns edges lane*4..+3.
        // b loads identical across the warp -> smem broadcast.
        unsigned long long acc[4][4];
#pragma unroll
        for (int i = 0; i < 4; i++)
#pragma unroll
            for (int n = 0; n < 4; n++) acc[i][n] = 0ULL;

#pragma unroll 4
        for (int jj = 0; jj < 64; jj++) {
            float4 a = *(const float4*)&u[jj * 132 + lane * 4];
            const unsigned long long* bp =
                (const unsigned long long*)&w2s[jj * 64 + wid * 8];
            unsigned long long b0 = bp[0], b1v = bp[1], b2v = bp[2], b3 = bp[3];
            float av[4] = {a.x, a.y, a.z, a.w};
#pragma unroll
            for (int i = 0; i < 4; i++) {
                unsigned long long ap = pack2(av[i], av[i]);
                fma2(acc[i][0], ap, b0);
                fma2(acc[i][1], ap, b1v);
                fma2(acc[i][2], ap, b2v);
                fma2(acc[i][3], ap, b3);
            }
        }
        __syncthreads();  // all reads of u done before overwrite with msh

#pragma unroll
        for (int i = 0; i < 4; i++) {
            int e = lane * 4 + i;
            unsigned long long* mp = (unsigned long long*)&msh[e * 68 + wid * 8];
#pragma unroll
            for (int n = 0; n < 4; n++) mp[n] = acc[i][n];
        }
        __syncthreads();

        // Phase C: per-(col-run, k) max; flush via atomicMax (positive-float-as-int)
        {
            int k = tid & 63;
            int part = tid >> 6;
            float mx = -3.0e38f;
            int cur = -1;
            for (int e = part * 32; e < part * 32 + 32; e++) {
                int c = cols[e];
                if (c != cur) {
                    if (cur >= 0) {
                        float v = mx + b2s[k];
                        if (v > 0.f) atomicMax((int*)&d_h2[cur * 64 + k], __float_as_int(v));
                    }
                    cur = c;
                    mx = -3.0e38f;
                }
                mx = fmaxf(mx, msh[e * 68 + k]);
            }
            if (cur >= 0) {
                float v = mx + b2s[k];
                if (v > 0.f) atomicMax((int*)&d_h2[cur * 64 + k], __float_as_int(v));
            }
        }
    }
}

// z = h2 @ gcn2_w; then zero this block's h2 chunk for next call
__global__ void k_z(const float* __restrict__ w) {
    __shared__ float ws[CH * COUT];
    for (int i = threadIdx.x; i < CH * COUT; i += blockDim.x) ws[i] = w[i];
    __syncthreads();
    int t = blockIdx.x * blockDim.x + threadIdx.x;   // grid exactly NN*COUT
    int c = t >> 4, k = t & 15;
    const float* hr = &d_h2[c * CH];
    float acc = 0.f;
#pragma unroll 8
    for (int j = 0; j < CH; j++) acc += hr[j] * ws[j * COUT + k];
    d_z[t] = acc;
    __syncthreads();
    float4* hz = (float4*)&d_h2[(size_t)blockIdx.x * 1024];
    hz[threadIdx.x] = make_float4(0.f, 0.f, 0.f, 0.f);
}

// out[c] = dinv[c]*(sum_r dinv[r]*z[r] + dinv[c]*z[c]) + b ; 2 nodes per warp
__global__ void k_out(const float* __restrict__ b, float* __restrict__ out) {
    int gw = (blockIdx.x * blockDim.x + threadIdx.x) >> 5;
    int lane = threadIdx.x & 31;
    int c = gw * 2 + (lane >> 4);
    int l = lane & 15;
    if (c >= NN) return;
    int beg = d_rowptr[c], end = d_rowptr[c + 1];
    float s0 = 0.f, s1 = 0.f;
    int i = beg;
    for (; i + 1 < end; i += 2) {
        int2 e0 = __ldg(&d_edge[i]);
        int2 e1 = __ldg(&d_edge[i + 1]);
        s0 += __ldg(&d_dinv[e0.x]) * __ldg(&d_z[e0.x * COUT + l]);
        s1 += __ldg(&d_dinv[e1.x]) * __ldg(&d_z[e1.x * COUT + l]);
    }
    if (i < end) {
        int2 e0 = __ldg(&d_edge[i]);
        s0 += __ldg(&d_dinv[e0.x]) * __ldg(&d_z[e0.x * COUT + l]);
    }
    float dc = d_dinv[c];
    out[c * COUT + l] = dc * (s0 + s1 + dc * d_z[c * COUT + l]) + b[l];
}

// ---------------- launch ----------------
extern "C" void kernel_launch(void* const* d_in, const int* in_sizes, int n_in,
                              void* d_out, int out_size) {
    const float* x   = (const float*)d_in[0];
    const int*   ei  = (const int*)d_in[1];
    const float* g1w = (const float*)d_in[2];
    const float* g1b = (const float*)d_in[3];
    const float* e1w = (const float*)d_in[4];
    const float* e1b = (const float*)d_in[5];
    const float* e2w = (const float*)d_in[6];
    const float* e2b = (const float*)d_in[7];
    const float* g2w = (const float*)d_in[8];
    const float* g2b = (const float*)d_in[9];
    float* out = (float*)d_out;

    k_prep<<<(EE + 255) / 256, 256>>>(ei);
    k_scan1<<<SNB, SB>>>();
    k_scan2<<<1, 64>>>();
    k_scan3<<<SNB, SB>>>();
    k_scatter<<<(EE + 255) / 256, 256>>>(ei);
    k_h1<<<1184, 256>>>(x, g1w, g1b);

    int pqsmem = (64 * 128 + 64 + 64 * 68) * (int)sizeof(float);
    cudaFuncSetAttribute(k_pq, cudaFuncAttributeMaxDynamicSharedMemorySize, pqsmem);
    k_pq<<<(NN + 63) / 64, 256, pqsmem>>>(e1w, e1b);

    int smem = EC_FLTS * (int)sizeof(float);
    cudaFuncSetAttribute(k_edgeconv, cudaFuncAttributeMaxDynamicSharedMemorySize, smem);
    k_edgeconv<<<592, 256, smem>>>(e2w, e2b);

    k_z<<<(NN * COUT + 255) / 256, 256>>>(g2w);
    k_out<<<(NN * 16 + 255) / 256, 256>>>(g2b, out);
}